// round 8
// baseline (speedup 1.0000x reference)
#include <cuda_runtime.h>
#include <cstdint>

#define N_TOK  32768
#define KDIM   2048
#define NEXP   64
#define TOPK   6
#define TM     64
#define KC     32
#define NCHUNK (KDIM / KC)

// scratch for scores (allocation-free rule: __device__ global)
__device__ float g_scores[(size_t)N_TOK * NEXP];

// ---- packed fp32x2 helpers (Blackwell FFMA2 path) ----
__device__ __forceinline__ unsigned long long fma2(unsigned long long a,
                                                   unsigned long long b,
                                                   unsigned long long c) {
    unsigned long long d;
    asm("fma.rn.f32x2 %0, %1, %2, %3;" : "=l"(d) : "l"(a), "l"(b), "l"(c));
    return d;
}
__device__ __forceinline__ unsigned long long packff(float lo, float hi) {
    unsigned long long r;
    asm("mov.b64 %0, {%1, %2};" : "=l"(r) : "f"(lo), "f"(hi));
    return r;
}
__device__ __forceinline__ float2 unpackff(unsigned long long v) {
    float2 f;
    asm("mov.b64 {%0, %1}, %2;" : "=f"(f.x), "=f"(f.y) : "l"(v));
    return f;
}

// ============================================================
// Kernel 1: scores[t][e] = sum_d x[t][d] * w[e][d]   (fp32)
// CTA tile: 64 tokens x 64 experts, 256 threads, 4x4 per thread
// (weights-validated at 8.7e-6)
// ============================================================
__global__ __launch_bounds__(256, 3)
void gemm_scores_kernel(const float* __restrict__ x, const float* __restrict__ w) {
    __shared__ float As[KC][TM];    // [k][token]
    __shared__ float Bs[KC][NEXP];  // [k][expert]

    const int tid = threadIdx.x;
    const int t0  = blockIdx.x * TM;
    const int lt  = tid & 63;
    const int lk  = (tid >> 6) << 2;

    const float* ag = x + (size_t)(t0 + lt) * KDIM + lk;
    const float* bg = w + (size_t)lt * KDIM + lk;

    const int tx = (tid & 15) << 2;
    const int ty = (tid >> 4) << 2;

    unsigned long long acc[2][4];
#pragma unroll
    for (int p = 0; p < 2; p++)
#pragma unroll
        for (int e = 0; e < 4; e++) acc[p][e] = 0ull;

    float4 ra0 = *(const float4*)(ag);
    float4 ra1 = *(const float4*)(ag + 16);
    float4 rb0 = *(const float4*)(bg);
    float4 rb1 = *(const float4*)(bg + 16);

    for (int c = 0; c < NCHUNK; c++) {
        __syncthreads();
        As[lk + 0][lt] = ra0.x;  As[lk + 1][lt] = ra0.y;
        As[lk + 2][lt] = ra0.z;  As[lk + 3][lt] = ra0.w;
        As[lk + 16][lt] = ra1.x; As[lk + 17][lt] = ra1.y;
        As[lk + 18][lt] = ra1.z; As[lk + 19][lt] = ra1.w;
        Bs[lk + 0][lt] = rb0.x;  Bs[lk + 1][lt] = rb0.y;
        Bs[lk + 2][lt] = rb0.z;  Bs[lk + 3][lt] = rb0.w;
        Bs[lk + 16][lt] = rb1.x; Bs[lk + 17][lt] = rb1.y;
        Bs[lk + 18][lt] = rb1.z; Bs[lk + 19][lt] = rb1.w;
        __syncthreads();

        if (c + 1 < NCHUNK) {
            const float* ag2 = ag + (c + 1) * KC;
            const float* bg2 = bg + (c + 1) * KC;
            ra0 = *(const float4*)(ag2);
            ra1 = *(const float4*)(ag2 + 16);
            rb0 = *(const float4*)(bg2);
            rb1 = *(const float4*)(bg2 + 16);
        }

#pragma unroll
        for (int kk = 0; kk < KC; kk++) {
            float4 av = *(const float4*)&As[kk][ty];
            float4 bv = *(const float4*)&Bs[kk][tx];
            unsigned long long a01 = packff(av.x, av.y);
            unsigned long long a23 = packff(av.z, av.w);
            float bvv[4] = {bv.x, bv.y, bv.z, bv.w};
#pragma unroll
            for (int e = 0; e < 4; e++) {
                unsigned long long bb = packff(bvv[e], bvv[e]);
                acc[0][e] = fma2(a01, bb, acc[0][e]);
                acc[1][e] = fma2(a23, bb, acc[1][e]);
            }
        }
    }

#pragma unroll
    for (int p = 0; p < 2; p++) {
#pragma unroll
        for (int e = 0; e < 4; e++) {
            float2 v = unpackff(acc[p][e]);
            g_scores[(size_t)(t0 + ty + 2 * p)     * NEXP + tx + e] = v.x;
            g_scores[(size_t)(t0 + ty + 2 * p + 1) * NEXP + tx + e] = v.y;
        }
    }
}

// FTZ emulation of XLA-GPU softmax tail:
//  - exp computed accurately (double -> float), but any result below
//    FLT_MIN flushes to exactly 0.0 (ftz expf: cutoff at x < -87.3365...)
//  - division result below FLT_MIN also flushes to 0.0 (ftz div)
// All flushed experts tie at 0.0 -> top_k stable order = ascending index.
#define FLT_MIN_N 1.17549435082228751e-38f
__device__ __forceinline__ float exp_ftz(float x) {
    float e = (float)exp((double)x);
    return (e < FLT_MIN_N) ? 0.0f : e;
}

// ============================================================
// Kernel 2: softmax over 64 experts + top-6 (warp per token).
// out: [N_TOK*TOPK] weights fp32, then [N_TOK*TOPK] indices as fp32
// ============================================================
__global__ __launch_bounds__(256)
void softmax_topk_kernel(float* __restrict__ out, int write_idx) {
    const int warp = threadIdx.x >> 5;
    const int lane = threadIdx.x & 31;
    const int t = blockIdx.x * 8 + warp;
    if (t >= N_TOK) return;

    const float* s = g_scores + (size_t)t * NEXP;
    float v0 = s[lane];
    float v1 = s[lane + 32];

    float m = fmaxf(v0, v1);
#pragma unroll
    for (int o = 16; o; o >>= 1) m = fmaxf(m, __shfl_xor_sync(0xffffffffu, m, o));

    float e0 = exp_ftz(v0 - m);
    float e1 = exp_ftz(v1 - m);
    float sum = e0 + e1;
#pragma unroll
    for (int o = 16; o; o >>= 1) sum += __shfl_xor_sync(0xffffffffu, sum, o);

    float p0 = __fdiv_rn(e0, sum);
    float p1 = __fdiv_rn(e1, sum);
    if (p0 < FLT_MIN_N) p0 = 0.0f;   // ftz division output
    if (p1 < FLT_MIN_N) p1 = 0.0f;

#pragma unroll
    for (int j = 0; j < TOPK; j++) {
        float bv; int bi;
        if (p0 >= p1) { bv = p0; bi = lane; }       // tie -> smaller index
        else          { bv = p1; bi = lane + 32; }
#pragma unroll
        for (int o = 16; o; o >>= 1) {
            float ov = __shfl_xor_sync(0xffffffffu, bv, o);
            int   oi = __shfl_xor_sync(0xffffffffu, bi, o);
            if (ov > bv || (ov == bv && oi < bi)) { bv = ov; bi = oi; }
        }
        if (lane == 0) {
            out[(size_t)t * TOPK + j] = bv;          // ROUTE_SCALE = 1
            if (write_idx)
                out[(size_t)N_TOK * TOPK + (size_t)t * TOPK + j] = (float)bi;
        }
        if (bi == lane)      p0 = -1.0f;
        if (bi == lane + 32) p1 = -1.0f;
    }
}

extern "C" void kernel_launch(void* const* d_in, const int* in_sizes, int n_in,
                              void* d_out, int out_size) {
    const float* x = (const float*)d_in[0];   // [32768, 2048] fp32
    const float* w = (const float*)d_in[1];   // [64, 2048] fp32
    float* out = (float*)d_out;

    gemm_scores_kernel<<<N_TOK / TM, 256>>>(x, w);

    const int write_idx = (out_size >= 2 * N_TOK * TOPK) ? 1 : 0;
    softmax_topk_kernel<<<N_TOK / 8, 256>>>(out, write_idx);
}

// round 9
// speedup vs baseline: 1.0006x; 1.0006x over previous
#include <cuda_runtime.h>
#include <cstdint>

#define N_TOK  32768
#define KDIM   2048
#define NEXP   64
#define TOPK   6
#define TM     64
#define KC     32
#define NCHUNK (KDIM / KC)

// scratch for scores (allocation-free rule: __device__ global)
__device__ float g_scores[(size_t)N_TOK * NEXP];

// ---- packed fp32x2 helpers (Blackwell FFMA2 path) ----
__device__ __forceinline__ unsigned long long fma2(unsigned long long a,
                                                   unsigned long long b,
                                                   unsigned long long c) {
    unsigned long long d;
    asm("fma.rn.f32x2 %0, %1, %2, %3;" : "=l"(d) : "l"(a), "l"(b), "l"(c));
    return d;
}
__device__ __forceinline__ unsigned long long packff(float lo, float hi) {
    unsigned long long r;
    asm("mov.b64 %0, {%1, %2};" : "=l"(r) : "f"(lo), "f"(hi));
    return r;
}
__device__ __forceinline__ float2 unpackff(unsigned long long v) {
    float2 f;
    asm("mov.b64 {%0, %1}, %2;" : "=f"(f.x), "=f"(f.y) : "l"(v));
    return f;
}

// ============================================================
// Kernel 1: scores[t][e] = sum_d x[t][d] * w[e][d]   (fp32)
// CTA tile: 64 tokens x 64 experts, 256 threads, 4x4 per thread
// (weights-validated at 8.7e-6)
// ============================================================
__global__ __launch_bounds__(256, 3)
void gemm_scores_kernel(const float* __restrict__ x, const float* __restrict__ w) {
    __shared__ float As[KC][TM];    // [k][token]
    __shared__ float Bs[KC][NEXP];  // [k][expert]

    const int tid = threadIdx.x;
    const int t0  = blockIdx.x * TM;
    const int lt  = tid & 63;
    const int lk  = (tid >> 6) << 2;

    const float* ag = x + (size_t)(t0 + lt) * KDIM + lk;
    const float* bg = w + (size_t)lt * KDIM + lk;

    const int tx = (tid & 15) << 2;
    const int ty = (tid >> 4) << 2;

    unsigned long long acc[2][4];
#pragma unroll
    for (int p = 0; p < 2; p++)
#pragma unroll
        for (int e = 0; e < 4; e++) acc[p][e] = 0ull;

    float4 ra0 = *(const float4*)(ag);
    float4 ra1 = *(const float4*)(ag + 16);
    float4 rb0 = *(const float4*)(bg);
    float4 rb1 = *(const float4*)(bg + 16);

    for (int c = 0; c < NCHUNK; c++) {
        __syncthreads();
        As[lk + 0][lt] = ra0.x;  As[lk + 1][lt] = ra0.y;
        As[lk + 2][lt] = ra0.z;  As[lk + 3][lt] = ra0.w;
        As[lk + 16][lt] = ra1.x; As[lk + 17][lt] = ra1.y;
        As[lk + 18][lt] = ra1.z; As[lk + 19][lt] = ra1.w;
        Bs[lk + 0][lt] = rb0.x;  Bs[lk + 1][lt] = rb0.y;
        Bs[lk + 2][lt] = rb0.z;  Bs[lk + 3][lt] = rb0.w;
        Bs[lk + 16][lt] = rb1.x; Bs[lk + 17][lt] = rb1.y;
        Bs[lk + 18][lt] = rb1.z; Bs[lk + 19][lt] = rb1.w;
        __syncthreads();

        if (c + 1 < NCHUNK) {
            const float* ag2 = ag + (c + 1) * KC;
            const float* bg2 = bg + (c + 1) * KC;
            ra0 = *(const float4*)(ag2);
            ra1 = *(const float4*)(ag2 + 16);
            rb0 = *(const float4*)(bg2);
            rb1 = *(const float4*)(bg2 + 16);
        }

#pragma unroll
        for (int kk = 0; kk < KC; kk++) {
            float4 av = *(const float4*)&As[kk][ty];
            float4 bv = *(const float4*)&Bs[kk][tx];
            unsigned long long a01 = packff(av.x, av.y);
            unsigned long long a23 = packff(av.z, av.w);
            float bvv[4] = {bv.x, bv.y, bv.z, bv.w};
#pragma unroll
            for (int e = 0; e < 4; e++) {
                unsigned long long bb = packff(bvv[e], bvv[e]);
                acc[0][e] = fma2(a01, bb, acc[0][e]);
                acc[1][e] = fma2(a23, bb, acc[1][e]);
            }
        }
    }

#pragma unroll
    for (int p = 0; p < 2; p++) {
#pragma unroll
        for (int e = 0; e < 4; e++) {
            float2 v = unpackff(acc[p][e]);
            g_scores[(size_t)(t0 + ty + 2 * p)     * NEXP + tx + e] = v.x;
            g_scores[(size_t)(t0 + ty + 2 * p + 1) * NEXP + tx + e] = v.y;
        }
    }
}

// FTZ emulation of XLA-GPU softmax tail:
//  - exp computed accurately (double -> float), but any result below
//    FLT_MIN flushes to exactly 0.0 (ftz expf: cutoff at x < -87.3365...)
//  - division result below FLT_MIN also flushes to 0.0 (ftz div)
// All flushed experts tie at 0.0 -> top_k stable order = ascending index.
#define FLT_MIN_N 1.17549435082228751e-38f
__device__ __forceinline__ float exp_ftz(float x) {
    float e = (float)exp((double)x);
    return (e < FLT_MIN_N) ? 0.0f : e;
}

// ============================================================
// Kernel 2: softmax over 64 experts + top-6 (warp per token).
// out: [N_TOK*TOPK] weights fp32, then [N_TOK*TOPK] indices as fp32
// ============================================================
__global__ __launch_bounds__(256)
void softmax_topk_kernel(float* __restrict__ out, int write_idx) {
    const int warp = threadIdx.x >> 5;
    const int lane = threadIdx.x & 31;
    const int t = blockIdx.x * 8 + warp;
    if (t >= N_TOK) return;

    const float* s = g_scores + (size_t)t * NEXP;
    float v0 = s[lane];
    float v1 = s[lane + 32];

    float m = fmaxf(v0, v1);
#pragma unroll
    for (int o = 16; o; o >>= 1) m = fmaxf(m, __shfl_xor_sync(0xffffffffu, m, o));

    float e0 = exp_ftz(v0 - m);
    float e1 = exp_ftz(v1 - m);
    float sum = e0 + e1;
#pragma unroll
    for (int o = 16; o; o >>= 1) sum += __shfl_xor_sync(0xffffffffu, sum, o);

    float p0 = __fdiv_rn(e0, sum);
    float p1 = __fdiv_rn(e1, sum);
    if (p0 < FLT_MIN_N) p0 = 0.0f;   // ftz division output
    if (p1 < FLT_MIN_N) p1 = 0.0f;

#pragma unroll
    for (int j = 0; j < TOPK; j++) {
        float bv; int bi;
        if (p0 >= p1) { bv = p0; bi = lane; }       // tie -> smaller index
        else          { bv = p1; bi = lane + 32; }
#pragma unroll
        for (int o = 16; o; o >>= 1) {
            float ov = __shfl_xor_sync(0xffffffffu, bv, o);
            int   oi = __shfl_xor_sync(0xffffffffu, bi, o);
            if (ov > bv || (ov == bv && oi < bi)) { bv = ov; bi = oi; }
        }
        if (lane == 0) {
            out[(size_t)t * TOPK + j] = bv;          // ROUTE_SCALE = 1
            if (write_idx)
                out[(size_t)N_TOK * TOPK + (size_t)t * TOPK + j] = (float)bi;
        }
        if (bi == lane)      p0 = -1.0f;
        if (bi == lane + 32) p1 = -1.0f;
    }
}

extern "C" void kernel_launch(void* const* d_in, const int* in_sizes, int n_in,
                              void* d_out, int out_size) {
    const float* x = (const float*)d_in[0];   // [32768, 2048] fp32
    const float* w = (const float*)d_in[1];   // [64, 2048] fp32
    float* out = (float*)d_out;

    gemm_scores_kernel<<<N_TOK / TM, 256>>>(x, w);

    const int write_idx = (out_size >= 2 * N_TOK * TOPK) ? 1 : 0;
    softmax_topk_kernel<<<N_TOK / 8, 256>>>(out, write_idx);
}

// round 10
// speedup vs baseline: 1.6839x; 1.6828x over previous
#include <cuda_runtime.h>
#include <cstdint>

#define N_TOK  32768
#define KDIM   2048
#define NEXP   64
#define TOPK   6
#define TM     128             // tokens per CTA
#define KC     32              // K per staged chunk
#define NCHUNK (KDIM / KC)     // 64
#define LDROW  130             // padded smem row (floats), even for LDS.64 align

// scratch for scores (allocation-free rule: __device__ global)
__device__ float g_scores[(size_t)N_TOK * NEXP];

// ---- packed fp32x2 helpers (Blackwell FFMA2 path) ----
__device__ __forceinline__ unsigned long long fma2(unsigned long long a,
                                                   unsigned long long b,
                                                   unsigned long long c) {
    unsigned long long d;
    asm("fma.rn.f32x2 %0, %1, %2, %3;" : "=l"(d) : "l"(a), "l"(b), "l"(c));
    return d;
}
__device__ __forceinline__ float2 unpackff(unsigned long long v) {
    float2 f;
    asm("mov.b64 {%0, %1}, %2;" : "=f"(f.x), "=f"(f.y) : "l"(v));
    return f;
}

// ============================================================
// Kernel 1: scores[t][e] = sum_d x[t][d] * w[e][d]   (fp32)
// CTA: 128 tokens x 64 experts, 128 threads, thread tile 8x8.
// B duplicated in smem so LDS.64 yields (b,b) with no pack MOVs.
// Accumulation: single ascending-k FFMA.rn chain per element ->
// bitwise identical scores to the validated round-9 kernel.
// ============================================================
__global__ __launch_bounds__(128, 2)
void gemm_scores_kernel(const float* __restrict__ x, const float* __restrict__ w) {
    __shared__ float As[KC][LDROW];   // [k][token], 128 used + pad
    __shared__ float Bd[KC][LDROW];   // [k][2*expert] duplicated + pad

    const int tid = threadIdx.x;
    const int tx  = tid & 7;          // expert group (strided experts: 8j+tx)
    const int ty  = tid >> 3;         // token group (tokens ty*8 .. ty*8+7)
    const int t0  = blockIdx.x * TM;

    // acc[p][j]: token pair (ty*8+2p, +1)  x  expert (8j+tx)
    unsigned long long acc[4][8];
#pragma unroll
    for (int p = 0; p < 4; p++)
#pragma unroll
        for (int j = 0; j < 8; j++) acc[p][j] = 0ull;

    // ---- staging prefetch (chunk 0) ----
    float4 ra[8], rb[4];
#pragma unroll
    for (int i = 0; i < 8; i++) {
        int gi = tid + 128 * i, row = gi >> 3, c16 = gi & 7;
        ra[i] = *(const float4*)(x + (size_t)(t0 + row) * KDIM + c16 * 4);
    }
#pragma unroll
    for (int i = 0; i < 4; i++) {
        int gi = tid + 128 * i, row = gi >> 3, c16 = gi & 7;
        rb[i] = *(const float4*)(w + (size_t)row * KDIM + c16 * 4);
    }

    for (int c = 0; c < NCHUNK; c++) {
        __syncthreads();   // previous compute done before overwrite
        // store A transposed: As[k][token]
#pragma unroll
        for (int i = 0; i < 8; i++) {
            int gi = tid + 128 * i, row = gi >> 3, k4 = (gi & 7) * 4;
            As[k4 + 0][row] = ra[i].x;
            As[k4 + 1][row] = ra[i].y;
            As[k4 + 2][row] = ra[i].z;
            As[k4 + 3][row] = ra[i].w;
        }
        // store B transposed + duplicated: Bd[k][2e]=Bd[k][2e+1]=w[e][k]
#pragma unroll
        for (int i = 0; i < 4; i++) {
            int gi = tid + 128 * i, row = gi >> 3, k4 = (gi & 7) * 4;
            *(float2*)&Bd[k4 + 0][2 * row] = make_float2(rb[i].x, rb[i].x);
            *(float2*)&Bd[k4 + 1][2 * row] = make_float2(rb[i].y, rb[i].y);
            *(float2*)&Bd[k4 + 2][2 * row] = make_float2(rb[i].z, rb[i].z);
            *(float2*)&Bd[k4 + 3][2 * row] = make_float2(rb[i].w, rb[i].w);
        }
        __syncthreads();

        // prefetch next chunk (overlaps with compute)
        if (c + 1 < NCHUNK) {
            const int k0 = (c + 1) * KC;
#pragma unroll
            for (int i = 0; i < 8; i++) {
                int gi = tid + 128 * i, row = gi >> 3, c16 = gi & 7;
                ra[i] = *(const float4*)(x + (size_t)(t0 + row) * KDIM + k0 + c16 * 4);
            }
#pragma unroll
            for (int i = 0; i < 4; i++) {
                int gi = tid + 128 * i, row = gi >> 3, c16 = gi & 7;
                rb[i] = *(const float4*)(w + (size_t)row * KDIM + k0 + c16 * 4);
            }
        }

        // compute: 32 k-steps, ascending (bitwise-stable accumulation)
#pragma unroll 8
        for (int kk = 0; kk < KC; kk++) {
            unsigned long long a[4], b[8];
#pragma unroll
            for (int p = 0; p < 4; p++)
                a[p] = *(const unsigned long long*)&As[kk][ty * 8 + 2 * p];
#pragma unroll
            for (int j = 0; j < 8; j++)
                b[j] = *(const unsigned long long*)&Bd[kk][2 * (8 * j + tx)];
#pragma unroll
            for (int p = 0; p < 4; p++)
#pragma unroll
                for (int j = 0; j < 8; j++)
                    acc[p][j] = fma2(a[p], b[j], acc[p][j]);
        }
    }

    // epilogue
#pragma unroll
    for (int p = 0; p < 4; p++) {
        const int tok = t0 + ty * 8 + 2 * p;
#pragma unroll
        for (int j = 0; j < 8; j++) {
            float2 v = unpackff(acc[p][j]);
            const int e = 8 * j + tx;
            g_scores[(size_t)tok * NEXP + e]       = v.x;
            g_scores[(size_t)(tok + 1) * NEXP + e] = v.y;
        }
    }
}

// FTZ emulation of XLA-GPU softmax tail (validated round 9):
// exp result below FLT_MIN flushes to exactly 0.0; division result
// below FLT_MIN flushes to 0.0. All flushed experts tie at 0.0 ->
// top_k stable order = ascending index.
#define FLT_MIN_N 1.17549435082228751e-38f
__device__ __forceinline__ float exp_ftz(float x) {
    float e = expf(x);                    // fast fp32 path (was fp64: 74us -> ~10us)
    return (e < FLT_MIN_N) ? 0.0f : e;
}

// ============================================================
// Kernel 2: softmax over 64 experts + top-6 (warp per token).
// out: [N_TOK*TOPK] weights fp32, then [N_TOK*TOPK] indices as fp32
// ============================================================
__global__ __launch_bounds__(256)
void softmax_topk_kernel(float* __restrict__ out, int write_idx) {
    const int warp = threadIdx.x >> 5;
    const int lane = threadIdx.x & 31;
    const int t = blockIdx.x * 8 + warp;
    if (t >= N_TOK) return;

    const float* s = g_scores + (size_t)t * NEXP;
    float v0 = s[lane];
    float v1 = s[lane + 32];

    float m = fmaxf(v0, v1);
#pragma unroll
    for (int o = 16; o; o >>= 1) m = fmaxf(m, __shfl_xor_sync(0xffffffffu, m, o));

    float e0 = exp_ftz(v0 - m);
    float e1 = exp_ftz(v1 - m);
    float sum = e0 + e1;
#pragma unroll
    for (int o = 16; o; o >>= 1) sum += __shfl_xor_sync(0xffffffffu, sum, o);

    float p0 = __fdiv_rn(e0, sum);
    float p1 = __fdiv_rn(e1, sum);
    if (p0 < FLT_MIN_N) p0 = 0.0f;   // ftz division output
    if (p1 < FLT_MIN_N) p1 = 0.0f;

#pragma unroll
    for (int j = 0; j < TOPK; j++) {
        float bv; int bi;
        if (p0 >= p1) { bv = p0; bi = lane; }       // tie -> smaller index
        else          { bv = p1; bi = lane + 32; }
#pragma unroll
        for (int o = 16; o; o >>= 1) {
            float ov = __shfl_xor_sync(0xffffffffu, bv, o);
            int   oi = __shfl_xor_sync(0xffffffffu, bi, o);
            if (ov > bv || (ov == bv && oi < bi)) { bv = ov; bi = oi; }
        }
        if (lane == 0) {
            out[(size_t)t * TOPK + j] = bv;          // ROUTE_SCALE = 1
            if (write_idx)
                out[(size_t)N_TOK * TOPK + (size_t)t * TOPK + j] = (float)bi;
        }
        if (bi == lane)      p0 = -1.0f;
        if (bi == lane + 32) p1 = -1.0f;
    }
}

extern "C" void kernel_launch(void* const* d_in, const int* in_sizes, int n_in,
                              void* d_out, int out_size) {
    const float* x = (const float*)d_in[0];   // [32768, 2048] fp32
    const float* w = (const float*)d_in[1];   // [64, 2048] fp32
    float* out = (float*)d_out;

    gemm_scores_kernel<<<N_TOK / TM, 128>>>(x, w);

    const int write_idx = (out_size >= 2 * N_TOK * TOPK) ? 1 : 0;
    softmax_topk_kernel<<<N_TOK / 8, 256>>>(out, write_idx);
}